// round 1
// baseline (speedup 1.0000x reference)
#include <cuda_runtime.h>
#include <math.h>

#define B_  32
#define T_  128
#define V_  16000
#define E_  512
#define H_  1024
#define F_  2048
#define G4  4096   // 4*H

// ---------------- scratch (device globals: no allocation allowed) ----------
__device__ float g_pooled[B_ * F_];                    // 32x2048
__device__ float g_init[B_ * 2 * H_];                  // 32x2048
__device__ float g_h[2][B_ * H_];                      // double-buffered hidden
__device__ float g_c[B_ * H_];                         // cell state (in-place)
__device__ float g_bsum[G4];                           // b_ih + b_hh
__device__ int   g_idx[B_ * T_];                       // input token index per (b,t)
__device__ float g_xproj[(size_t)B_ * T_ * G4];        // 4096 x 4096 (67 MB)
__device__ float g_hs[(size_t)B_ * T_ * H_];           // 4096 x 1024 (16.8 MB)

// ---------------- pooling: mean over 7x7 ------------------------------------
__global__ void pool_kernel(const float* __restrict__ feat) {
    int i = blockIdx.x * blockDim.x + threadIdx.x;
    if (i >= B_ * F_) return;
    const float* p = feat + (size_t)i * 49;
    float s = 0.f;
#pragma unroll
    for (int k = 0; k < 49; k++) s += p[k];
    g_pooled[i] = s * (1.0f / 49.0f);
}

// ---------------- prep: split init -> h0/c0, bsum, token indices ------------
__global__ void prep_kernel(const int* __restrict__ reports,
                            const float* __restrict__ b_ih,
                            const float* __restrict__ b_hh) {
    int j = blockIdx.x * blockDim.x + threadIdx.x;
    if (j < B_ * H_) {
        int b = j >> 10;
        int u = j & (H_ - 1);
        g_h[0][j] = g_init[b * 2 * H_ + u];
        g_c[j]    = g_init[b * 2 * H_ + H_ + u];
    }
    if (j < G4) g_bsum[j] = b_ih[j] + b_hh[j];
    if (j < B_ * T_) g_idx[j] = ((j & (T_ - 1)) == 0) ? 1 : reports[j - 1];
}

// ---------------- generic NT SGEMM: C[m][n] = sum_k A[m][k]*B[n][k] + bias[n]
// A optionally row-gathered through ridx. 128x128x8 tile, 8x8 microtile, 256 thr.
template <bool GATHER>
__global__ void __launch_bounds__(256, 2)
sgemm_nt(const float* __restrict__ A, const float* __restrict__ Bm,
         const float* __restrict__ bias, float* __restrict__ C,
         int M, int N, int K, const int* __restrict__ ridx) {
    const int BM = 128, BN = 128, BK = 8;
    __shared__ float As[BK][BM + 4];
    __shared__ float Bs[BK][BN + 4];

    int bm = blockIdx.y * BM;
    int bn = blockIdx.x * BN;
    int tid = threadIdx.x;

    int lrow = tid >> 1;          // 0..127
    int lk   = (tid & 1) * 4;     // 0 or 4

    int am = bm + lrow;
    bool aval = (am < M);
    const float* Arow = A;
    if (aval) {
        int r = GATHER ? ridx[am] : am;
        Arow = A + (size_t)r * K;
    }
    const float* Brow = Bm + (size_t)(bn + lrow) * K;  // N tiles always full

    int tx = tid & 15;   // n
    int ty = tid >> 4;   // m

    float acc[8][8];
#pragma unroll
    for (int i = 0; i < 8; i++)
#pragma unroll
        for (int j = 0; j < 8; j++) acc[i][j] = 0.f;

    for (int k0 = 0; k0 < K; k0 += BK) {
        float4 av = aval ? *(const float4*)(Arow + k0 + lk)
                         : make_float4(0.f, 0.f, 0.f, 0.f);
        float4 bvv = *(const float4*)(Brow + k0 + lk);
        As[lk + 0][lrow] = av.x;  As[lk + 1][lrow] = av.y;
        As[lk + 2][lrow] = av.z;  As[lk + 3][lrow] = av.w;
        Bs[lk + 0][lrow] = bvv.x; Bs[lk + 1][lrow] = bvv.y;
        Bs[lk + 2][lrow] = bvv.z; Bs[lk + 3][lrow] = bvv.w;
        __syncthreads();

#pragma unroll
        for (int kk = 0; kk < BK; kk++) {
            float4 a0 = *(const float4*)&As[kk][ty * 8];
            float4 a1 = *(const float4*)&As[kk][ty * 8 + 4];
            float4 b0 = *(const float4*)&Bs[kk][tx * 8];
            float4 b1 = *(const float4*)&Bs[kk][tx * 8 + 4];
            float a[8] = {a0.x, a0.y, a0.z, a0.w, a1.x, a1.y, a1.z, a1.w};
            float b[8] = {b0.x, b0.y, b0.z, b0.w, b1.x, b1.y, b1.z, b1.w};
#pragma unroll
            for (int i = 0; i < 8; i++)
#pragma unroll
                for (int j = 0; j < 8; j++) acc[i][j] += a[i] * b[j];
        }
        __syncthreads();
    }

#pragma unroll
    for (int i = 0; i < 8; i++) {
        int m = bm + ty * 8 + i;
        if (m < M) {
            float* Crow = C + (size_t)m * N + bn + tx * 8;
#pragma unroll
            for (int j = 0; j < 8; j++)
                Crow[j] = acc[i][j] + bias[bn + tx * 8 + j];
        }
    }
}

// ---------------- fused LSTM step: gates = xproj + h@W_hh^T, then cell ------
// Block bi handles 8 hidden units (u0..u0+7) for all 4 gates x 32 batch.
// grid = 128 blocks, 256 threads.
__device__ __forceinline__ float sigmoidf_(float x) {
    return 1.f / (1.f + expf(-x));
}

__global__ void __launch_bounds__(256)
lstm_step_kernel(const float* __restrict__ W_hh, int t) {
    __shared__ float Ws[32][34];
    __shared__ float Hs[32][34];
    __shared__ float Gs[32][33];

    int tid = threadIdx.x;
    int u0 = blockIdx.x * 8;
    const float* hsrc = g_h[t & 1];
    float* hdst = g_h[(t + 1) & 1];

    // loaders: 32 rows x 32 k per tile; row = tid/8, float4 at (tid%8)*4
    int rl = tid >> 3;                 // 0..31 (gate-row local / batch for h)
    int k4 = (tid & 7) << 2;           // 0..28
    int grow = ((rl >> 3) << 10) + u0 + (rl & 7);  // global gate row
    const float* wrow = W_hh + (size_t)grow * H_;
    const float* hrow = hsrc + rl * H_;

    int ty = tid >> 4;   // 0..15 -> rows ty*2, ty*2+1
    int tx = tid & 15;   // 0..15 -> batches tx*2, tx*2+1

    float a00 = 0.f, a01 = 0.f, a10 = 0.f, a11 = 0.f;

    for (int k0 = 0; k0 < H_; k0 += 32) {
        float4 wv = *(const float4*)(wrow + k0 + k4);
        float4 hv = *(const float4*)(hrow + k0 + k4);
        Ws[k4 + 0][rl] = wv.x; Ws[k4 + 1][rl] = wv.y;
        Ws[k4 + 2][rl] = wv.z; Ws[k4 + 3][rl] = wv.w;
        Hs[k4 + 0][rl] = hv.x; Hs[k4 + 1][rl] = hv.y;
        Hs[k4 + 2][rl] = hv.z; Hs[k4 + 3][rl] = hv.w;
        __syncthreads();
#pragma unroll
        for (int kk = 0; kk < 32; kk++) {
            float2 av = *(const float2*)&Ws[kk][ty * 2];
            float2 bv = *(const float2*)&Hs[kk][tx * 2];
            a00 += av.x * bv.x;  a01 += av.x * bv.y;
            a10 += av.y * bv.x;  a11 += av.y * bv.y;
        }
        __syncthreads();
    }

    // add xproj, park gates in smem
    int r0 = ty * 2, b0 = tx * 2;
    int gr0 = ((r0 >> 3) << 10) + u0 + (r0 & 7);
    int gr1 = (((r0 + 1) >> 3) << 10) + u0 + ((r0 + 1) & 7);
    size_t x0 = ((size_t)(b0 * T_ + t)) * G4;
    size_t x1 = ((size_t)((b0 + 1) * T_ + t)) * G4;
    Gs[r0][b0]         = a00 + g_xproj[x0 + gr0];
    Gs[r0][b0 + 1]     = a01 + g_xproj[x1 + gr0];
    Gs[r0 + 1][b0]     = a10 + g_xproj[x0 + gr1];
    Gs[r0 + 1][b0 + 1] = a11 + g_xproj[x1 + gr1];
    __syncthreads();

    // cell update: thread -> (unit ui, batch bb)
    int ui = tid >> 5;     // 0..7
    int bb = tid & 31;     // 0..31
    float gi = Gs[ui][bb];
    float gf = Gs[8 + ui][bb];
    float gg = Gs[16 + ui][bb];
    float go = Gs[24 + ui][bb];

    int cix = bb * H_ + u0 + ui;
    float cv = g_c[cix];
    float cn = sigmoidf_(gf) * cv + sigmoidf_(gi) * tanhf(gg);
    float hn = sigmoidf_(go) * tanhf(cn);
    g_c[cix] = cn;
    hdst[cix] = hn;
    g_hs[((size_t)bb * T_ + t) * H_ + u0 + ui] = hn;
}

// ---------------- launcher ---------------------------------------------------
extern "C" void kernel_launch(void* const* d_in, const int* in_sizes, int n_in,
                              void* d_out, int out_size) {
    const float* features = (const float*)d_in[0];
    const int*   reports  = (const int*)d_in[1];
    const float* fc_W     = (const float*)d_in[2];
    const float* fc_b     = (const float*)d_in[3];
    const float* emb      = (const float*)d_in[4];
    const float* W_ih     = (const float*)d_in[5];
    const float* W_hh     = (const float*)d_in[6];
    const float* b_ih     = (const float*)d_in[7];
    const float* b_hh     = (const float*)d_in[8];
    const float* Wv       = (const float*)d_in[9];
    const float* bv       = (const float*)d_in[10];
    float* out = (float*)d_out;

    float *pooled_p, *init_p, *xproj_p, *hs_p, *bsum_p;
    int* idx_p;
    cudaGetSymbolAddress((void**)&pooled_p, g_pooled);
    cudaGetSymbolAddress((void**)&init_p,   g_init);
    cudaGetSymbolAddress((void**)&xproj_p,  g_xproj);
    cudaGetSymbolAddress((void**)&hs_p,     g_hs);
    cudaGetSymbolAddress((void**)&bsum_p,   g_bsum);
    cudaGetSymbolAddress((void**)&idx_p,    g_idx);

    // 1) pooling
    pool_kernel<<<(B_ * F_ + 255) / 256, 256>>>(features);

    // 2) fc init: init(32x2048) = pooled @ fc_W^T + fc_b
    sgemm_nt<false><<<dim3(F_ / 128, 1), 256>>>(
        pooled_p, fc_W, fc_b, init_p, B_, 2 * H_, F_, nullptr);

    // 3) prep: h0/c0 split, bsum, token indices
    prep_kernel<<<(B_ * H_ + 255) / 256, 256>>>(reports, b_ih, b_hh);

    // 4) xproj(4096x4096) = emb[idx] @ W_ih^T + (b_ih + b_hh)
    sgemm_nt<true><<<dim3(G4 / 128, (B_ * T_) / 128), 256>>>(
        emb, W_ih, bsum_p, xproj_p, B_ * T_, G4, E_, idx_p);

    // 5) 128 sequential LSTM steps
    for (int t = 0; t < T_; t++)
        lstm_step_kernel<<<128, 256>>>(W_hh, t);

    // 6) output projection: out(4096x16000) = hs @ Wv^T + bv
    sgemm_nt<false><<<dim3(V_ / 128, (B_ * T_) / 128), 256>>>(
        hs_p, Wv, bv, out, B_ * T_, V_, H_, nullptr);
}

// round 3
// speedup vs baseline: 1.3511x; 1.3511x over previous
#include <cuda_runtime.h>
#include <cuda_bf16.h>
#include <math.h>
#include <stdint.h>

#define B_  32
#define T_  128
#define V_  16000
#define E_  512
#define H_  1024
#define F_  2048
#define G4  4096   // 4*H
#define KC  3072   // 3*H for bf16-split GEMM
#define NKCH (KC / 32)   // 96 k-chunks of 32

// ---------------- scratch (device globals: no allocation allowed) ----------
__device__ float g_pooled[B_ * F_];
__device__ float g_init[B_ * 2 * H_];
__device__ float g_h[2][B_ * H_];
__device__ float g_c[B_ * H_];
__device__ float g_bsum[G4];
__device__ int   g_idx[B_ * T_];
__device__ float g_xproj[(size_t)B_ * T_ * G4];        // 67 MB
__device__ float g_hs[(size_t)B_ * T_ * H_];           // 16.8 MB
__device__ __nv_bfloat16 g_A2[(size_t)B_ * T_ * KC];   // 25 MB  [hi|hi|lo]
__device__ __nv_bfloat16 g_B2[(size_t)V_ * KC];        // 98 MB  [hi|lo|hi]

// ---------------- pooling ----------------------------------------------------
__global__ void pool_kernel(const float* __restrict__ feat) {
    int i = blockIdx.x * blockDim.x + threadIdx.x;
    if (i >= B_ * F_) return;
    const float* p = feat + (size_t)i * 49;
    float s = 0.f;
#pragma unroll
    for (int k = 0; k < 49; k++) s += p[k];
    g_pooled[i] = s * (1.0f / 49.0f);
}

// ---------------- prep --------------------------------------------------------
__global__ void prep_kernel(const int* __restrict__ reports,
                            const float* __restrict__ b_ih,
                            const float* __restrict__ b_hh) {
    int j = blockIdx.x * blockDim.x + threadIdx.x;
    if (j < B_ * H_) {
        int b = j >> 10;
        int u = j & (H_ - 1);
        g_h[0][j] = g_init[b * 2 * H_ + u];
        g_c[j]    = g_init[b * 2 * H_ + H_ + u];
    }
    if (j < G4) g_bsum[j] = b_ih[j] + b_hh[j];
    if (j < B_ * T_) g_idx[j] = ((j & (T_ - 1)) == 0) ? 1 : reports[j - 1];
}

// ---------------- generic NT SGEMM (fc init + xproj) --------------------------
template <bool GATHER>
__global__ void __launch_bounds__(256, 2)
sgemm_nt(const float* __restrict__ A, const float* __restrict__ Bm,
         const float* __restrict__ bias, float* __restrict__ C,
         int M, int N, int K, const int* __restrict__ ridx) {
    const int BM = 128, BN = 128, BK = 8;
    __shared__ float As[BK][BM + 4];
    __shared__ float Bs[BK][BN + 4];

    int bm = blockIdx.y * BM;
    int bn = blockIdx.x * BN;
    int tid = threadIdx.x;

    int lrow = tid >> 1;
    int lk   = (tid & 1) * 4;

    int am = bm + lrow;
    bool aval = (am < M);
    const float* Arow = A;
    if (aval) {
        int r = GATHER ? ridx[am] : am;
        Arow = A + (size_t)r * K;
    }
    const float* Brow = Bm + (size_t)(bn + lrow) * K;

    int tx = tid & 15;
    int ty = tid >> 4;

    float acc[8][8];
#pragma unroll
    for (int i = 0; i < 8; i++)
#pragma unroll
        for (int j = 0; j < 8; j++) acc[i][j] = 0.f;

    for (int k0 = 0; k0 < K; k0 += BK) {
        float4 av = aval ? *(const float4*)(Arow + k0 + lk)
                         : make_float4(0.f, 0.f, 0.f, 0.f);
        float4 bvv = *(const float4*)(Brow + k0 + lk);
        As[lk + 0][lrow] = av.x;  As[lk + 1][lrow] = av.y;
        As[lk + 2][lrow] = av.z;  As[lk + 3][lrow] = av.w;
        Bs[lk + 0][lrow] = bvv.x; Bs[lk + 1][lrow] = bvv.y;
        Bs[lk + 2][lrow] = bvv.z; Bs[lk + 3][lrow] = bvv.w;
        __syncthreads();

#pragma unroll
        for (int kk = 0; kk < BK; kk++) {
            float4 a0 = *(const float4*)&As[kk][ty * 8];
            float4 a1 = *(const float4*)&As[kk][ty * 8 + 4];
            float4 b0 = *(const float4*)&Bs[kk][tx * 8];
            float4 b1 = *(const float4*)&Bs[kk][tx * 8 + 4];
            float a[8] = {a0.x, a0.y, a0.z, a0.w, a1.x, a1.y, a1.z, a1.w};
            float b[8] = {b0.x, b0.y, b0.z, b0.w, b1.x, b1.y, b1.z, b1.w};
#pragma unroll
            for (int i = 0; i < 8; i++)
#pragma unroll
                for (int j = 0; j < 8; j++) acc[i][j] += a[i] * b[j];
        }
        __syncthreads();
    }

#pragma unroll
    for (int i = 0; i < 8; i++) {
        int m = bm + ty * 8 + i;
        if (m < M) {
            float* Crow = C + (size_t)m * N + bn + tx * 8;
#pragma unroll
            for (int j = 0; j < 8; j++)
                Crow[j] = acc[i][j] + bias[bn + tx * 8 + j];
        }
    }
}

// ---------------- fused LSTM step, split-K x2, 512 threads --------------------
__device__ __forceinline__ float sigmoidf_(float x) {
    return 1.f / (1.f + expf(-x));
}

__global__ void __launch_bounds__(512)
lstm_step2(const float* __restrict__ W_hh, int t) {
    __shared__ float Ws[2][32][34];
    __shared__ float Hs[2][32][34];
    __shared__ float Gs[2][32][33];

    int tid = threadIdx.x;
    int half = tid >> 8;
    int ltid = tid & 255;
    int u0 = blockIdx.x * 8;
    int koff = half * 512;
    const float* hsrc = g_h[t & 1];
    float* hdst = g_h[(t + 1) & 1];

    int rl = ltid >> 3;
    int k4 = (ltid & 7) << 2;
    int grow = ((rl >> 3) << 10) + u0 + (rl & 7);
    const float* wrow = W_hh + (size_t)grow * H_ + koff;
    const float* hrow = hsrc + rl * H_ + koff;

    int ty = ltid >> 4;
    int tx = ltid & 15;

    float a00 = 0.f, a01 = 0.f, a10 = 0.f, a11 = 0.f;

    for (int k0 = 0; k0 < 512; k0 += 32) {
        float4 wv = *(const float4*)(wrow + k0 + k4);
        float4 hv = *(const float4*)(hrow + k0 + k4);
        Ws[half][k4 + 0][rl] = wv.x; Ws[half][k4 + 1][rl] = wv.y;
        Ws[half][k4 + 2][rl] = wv.z; Ws[half][k4 + 3][rl] = wv.w;
        Hs[half][k4 + 0][rl] = hv.x; Hs[half][k4 + 1][rl] = hv.y;
        Hs[half][k4 + 2][rl] = hv.z; Hs[half][k4 + 3][rl] = hv.w;
        __syncthreads();
#pragma unroll
        for (int kk = 0; kk < 32; kk++) {
            float2 av = *(const float2*)&Ws[half][kk][ty * 2];
            float2 bv = *(const float2*)&Hs[half][kk][tx * 2];
            a00 += av.x * bv.x;  a01 += av.x * bv.y;
            a10 += av.y * bv.x;  a11 += av.y * bv.y;
        }
        __syncthreads();
    }

    int r0 = ty * 2, b0 = tx * 2;
    Gs[half][r0][b0]         = a00;
    Gs[half][r0][b0 + 1]     = a01;
    Gs[half][r0 + 1][b0]     = a10;
    Gs[half][r0 + 1][b0 + 1] = a11;
    __syncthreads();

    if (tid < 256) {
        int ui = tid >> 5;
        int bb = tid & 31;
        size_t xb = ((size_t)(bb * T_ + t)) << 12;
        float gi = Gs[0][ui][bb]      + Gs[1][ui][bb]      + g_xproj[xb + u0 + ui];
        float gf = Gs[0][8 + ui][bb]  + Gs[1][8 + ui][bb]  + g_xproj[xb + 1024 + u0 + ui];
        float gg = Gs[0][16 + ui][bb] + Gs[1][16 + ui][bb] + g_xproj[xb + 2048 + u0 + ui];
        float go = Gs[0][24 + ui][bb] + Gs[1][24 + ui][bb] + g_xproj[xb + 3072 + u0 + ui];

        int cix = bb * H_ + u0 + ui;
        float cv = g_c[cix];
        float cn = sigmoidf_(gf) * cv + sigmoidf_(gi) * tanhf(gg);
        float hn = sigmoidf_(go) * tanhf(cn);
        g_c[cix] = cn;
        hdst[cix] = hn;
        g_hs[((size_t)bb * T_ + t) * H_ + u0 + ui] = hn;
    }
}

// ---------------- bf16 split conversions -------------------------------------
__global__ void conv_hs_kernel() {
    int i = blockIdx.x * blockDim.x + threadIdx.x;
    if (i >= B_ * T_ * H_) return;
    float x = g_hs[i];
    int m = i >> 10, k = i & 1023;
    __nv_bfloat16 hi = __float2bfloat16(x);
    __nv_bfloat16 lo = __float2bfloat16(x - __bfloat162float(hi));
    __nv_bfloat16* r = g_A2 + (size_t)m * KC;
    r[k] = hi; r[k + 1024] = hi; r[k + 2048] = lo;
}
__global__ void conv_wv_kernel(const float* __restrict__ Wv) {
    int i = blockIdx.x * blockDim.x + threadIdx.x;
    if (i >= V_ * H_) return;
    float x = Wv[i];
    int m = i >> 10, k = i & 1023;
    __nv_bfloat16 hi = __float2bfloat16(x);
    __nv_bfloat16 lo = __float2bfloat16(x - __bfloat162float(hi));
    __nv_bfloat16* r = g_B2 + (size_t)m * KC;
    r[k] = hi; r[k + 1024] = lo; r[k + 2048] = hi;
}

// ---------------- mma.sync bf16 GEMM: out = A2 @ B2^T + bv --------------------
// A2: [4096, 3072] bf16, B2: [16000, 3072] bf16, C: [4096, 16000] f32.
// CTA 128x128, BK=32. 8 warps in 2(m) x 4(n); warp tile 64x32 via
// mma.m16n8k16 (4 m-tiles x 4 n-tiles). Smem rows 32 bf16 (=16 b32 = 8
// 8B-chunks), XOR-swizzled: chunk' = chunk ^ (row&6) -> conflict-free
// fragment loads, aligned uint4 stores. Register-prefetch double buffer.
__device__ __forceinline__ void mma_bf16(float* d, const uint32_t* a,
                                         const uint32_t* b) {
    asm volatile(
        "mma.sync.aligned.m16n8k16.row.col.f32.bf16.bf16.f32 "
        "{%0,%1,%2,%3}, {%4,%5,%6,%7}, {%8,%9}, {%0,%1,%2,%3};"
        : "+f"(d[0]), "+f"(d[1]), "+f"(d[2]), "+f"(d[3])
        : "r"(a[0]), "r"(a[1]), "r"(a[2]), "r"(a[3]), "r"(b[0]), "r"(b[1]));
}

#define XB32(row, kp) (((row) << 4) + ((kp) ^ (((row) & 6) << 1)))

__global__ void __launch_bounds__(256, 2)
mma_gemm_out(const __nv_bfloat16* __restrict__ A2,
             const __nv_bfloat16* __restrict__ B2,
             const float* __restrict__ bias,
             float* __restrict__ C) {
    __shared__ uint32_t sA[2][128 * 16];
    __shared__ uint32_t sB[2][128 * 16];

    int tid = threadIdx.x;
    int lane = tid & 31, w = tid >> 5;
    int g = lane >> 2, tig = lane & 3;
    int wm = w >> 2, wn = w & 3;

    int m0 = blockIdx.x * 128;
    int n0 = blockIdx.y * 128;

    // loader mapping: row = tid>>1 (0..127), half = tid&1
    int lrow = tid >> 1;
    int lhalf = tid & 1;
    const uint4* pa = (const uint4*)(A2 + (size_t)(m0 + lrow) * KC) + lhalf * 2;
    const uint4* pb = (const uint4*)(B2 + (size_t)(n0 + lrow) * KC) + lhalf * 2;
    // store b32 base indices for the 2 uint4s (u=0,1): chunk c = 4*half+2u
    int sw = lrow & 6;
    int st0 = (lrow << 4) + (((lhalf * 4 + 0) ^ sw) << 1);
    int st1 = (lrow << 4) + (((lhalf * 4 + 2) ^ sw) << 1);

    float acc[4][4][4];
#pragma unroll
    for (int i = 0; i < 4; i++)
#pragma unroll
        for (int j = 0; j < 4; j++)
#pragma unroll
            for (int q = 0; q < 4; q++) acc[i][j][q] = 0.f;

    uint4 ra0 = pa[0], ra1 = pa[1];
    uint4 rb0 = pb[0], rb1 = pb[1];

    for (int kc = 0; kc < NKCH; kc++) {
        int p = kc & 1;
        *(uint4*)&sA[p][st0] = ra0;
        *(uint4*)&sA[p][st1] = ra1;
        *(uint4*)&sB[p][st0] = rb0;
        *(uint4*)&sB[p][st1] = rb1;
        __syncthreads();

        if (kc + 1 < NKCH) {
            ra0 = pa[(kc + 1) * 4 + 0]; ra1 = pa[(kc + 1) * 4 + 1];
            rb0 = pb[(kc + 1) * 4 + 0]; rb1 = pb[(kc + 1) * 4 + 1];
        }

        const uint32_t* cA = sA[p];
        const uint32_t* cB = sB[p];
#pragma unroll
        for (int ks = 0; ks < 2; ks++) {
            int kp1 = ks * 8 + tig;
            int kp2 = kp1 + 4;
            uint32_t bf[4][2];
#pragma unroll
            for (int nt = 0; nt < 4; nt++) {
                int rb = wn * 32 + nt * 8 + g;
                bf[nt][0] = cB[XB32(rb, kp1)];
                bf[nt][1] = cB[XB32(rb, kp2)];
            }
#pragma unroll
            for (int mt = 0; mt < 4; mt++) {
                int r1 = wm * 64 + mt * 16 + g;
                int r2 = r1 + 8;
                uint32_t af[4];
                af[0] = cA[XB32(r1, kp1)];
                af[1] = cA[XB32(r2, kp1)];
                af[2] = cA[XB32(r1, kp2)];
                af[3] = cA[XB32(r2, kp2)];
#pragma unroll
                for (int nt = 0; nt < 4; nt++)
                    mma_bf16(acc[mt][nt], af, bf[nt]);
            }
        }
        __syncthreads();
    }

    // epilogue
#pragma unroll
    for (int mt = 0; mt < 4; mt++) {
#pragma unroll
        for (int i2 = 0; i2 < 2; i2++) {
            int row = m0 + wm * 64 + mt * 16 + g + i2 * 8;
            float* crow = C + (size_t)row * V_;
#pragma unroll
            for (int nt = 0; nt < 4; nt++) {
                int col = n0 + wn * 32 + nt * 8 + 2 * tig;
                float b0 = __ldg(&bias[col]);
                float b1 = __ldg(&bias[col + 1]);
                crow[col]     = acc[mt][nt][i2 * 2]     + b0;
                crow[col + 1] = acc[mt][nt][i2 * 2 + 1] + b1;
            }
        }
    }
}

// ---------------- launcher ---------------------------------------------------
extern "C" void kernel_launch(void* const* d_in, const int* in_sizes, int n_in,
                              void* d_out, int out_size) {
    const float* features = (const float*)d_in[0];
    const int*   reports  = (const int*)d_in[1];
    const float* fc_W     = (const float*)d_in[2];
    const float* fc_b     = (const float*)d_in[3];
    const float* emb      = (const float*)d_in[4];
    const float* W_ih     = (const float*)d_in[5];
    const float* W_hh     = (const float*)d_in[6];
    const float* b_ih     = (const float*)d_in[7];
    const float* b_hh     = (const float*)d_in[8];
    const float* Wv       = (const float*)d_in[9];
    const float* bv       = (const float*)d_in[10];
    float* out = (float*)d_out;

    float *pooled_p, *init_p, *xproj_p, *bsum_p;
    __nv_bfloat16 *A2_p, *B2_p;
    int* idx_p;
    cudaGetSymbolAddress((void**)&pooled_p, g_pooled);
    cudaGetSymbolAddress((void**)&init_p,   g_init);
    cudaGetSymbolAddress((void**)&xproj_p,  g_xproj);
    cudaGetSymbolAddress((void**)&bsum_p,   g_bsum);
    cudaGetSymbolAddress((void**)&idx_p,    g_idx);
    cudaGetSymbolAddress((void**)&A2_p,     g_A2);
    cudaGetSymbolAddress((void**)&B2_p,     g_B2);

    // 1) pooling
    pool_kernel<<<(B_ * F_ + 255) / 256, 256>>>(features);

    // 2) fc init
    sgemm_nt<false><<<dim3((2 * H_) / 128, 1), 256>>>(
        pooled_p, fc_W, fc_b, init_p, B_, 2 * H_, F_, nullptr);

    // 3) prep
    prep_kernel<<<(B_ * H_ + 255) / 256, 256>>>(reports, b_ih, b_hh);

    // 4) Wv -> bf16 split (independent of recurrence)
    conv_wv_kernel<<<(V_ * H_ + 255) / 256, 256>>>(Wv);

    // 5) xproj
    sgemm_nt<true><<<dim3(G4 / 128, (B_ * T_) / 128), 256>>>(
        emb, W_ih, bsum_p, xproj_p, B_ * T_, G4, E_, idx_p);

    // 6) 128 sequential LSTM steps
    for (int t = 0; t < T_; t++)
        lstm_step2<<<128, 512>>>(W_hh, t);

    // 7) hs -> bf16 split
    conv_hs_kernel<<<(B_ * T_ * H_ + 255) / 256, 256>>>();

    // 8) output projection on tensor cores (mma.sync bf16, K=3072 split)
    mma_gemm_out<<<dim3((B_ * T_) / 128, V_ / 128), 256>>>(
        A2_p, B2_p, bv, out);
}

// round 4
// speedup vs baseline: 1.7685x; 1.3089x over previous
#include <cuda_runtime.h>
#include <cuda_bf16.h>
#include <math.h>
#include <stdint.h>

#define B_  32
#define T_  128
#define V_  16000
#define E_  512
#define H_  1024
#define F_  2048
#define G4  4096   // 4*H
#define KC  3072   // 3*H for bf16-split GEMM
#define NKCH (KC / 32)   // 96 k-chunks of 32 (output GEMM)
#define NBLK 128         // persistent LSTM blocks (1 per SM, <=148)

// ---------------- scratch (device globals: no allocation allowed) ----------
__device__ float g_pooled[B_ * F_];
__device__ float g_init[B_ * 2 * H_];
__device__ float g_bsum[G4];
__device__ int   g_idx[B_ * T_];
__device__ float g_xproj[(size_t)B_ * T_ * G4];        // 67 MB
__device__ __nv_bfloat16 g_A2[(size_t)B_ * T_ * KC];   // 25 MB  [hi|hi|lo] per (b,t)
__device__ __nv_bfloat16 g_B2[(size_t)V_ * KC];        // 98 MB  [hi|lo|hi]
__device__ __nv_bfloat16 g_W2[(size_t)G4 * KC];        // 25 MB  [hi|lo|hi] of W_hh
__device__ __nv_bfloat16 g_A0[B_ * KC];                // h0 split [hi|hi|lo]
__device__ unsigned int  g_barcnt;

// ---------------- pooling ----------------------------------------------------
__global__ void pool_kernel(const float* __restrict__ feat) {
    int i = blockIdx.x * blockDim.x + threadIdx.x;
    if (i >= B_ * F_) return;
    const float* p = feat + (size_t)i * 49;
    float s = 0.f;
#pragma unroll
    for (int k = 0; k < 49; k++) s += p[k];
    g_pooled[i] = s * (1.0f / 49.0f);
}

// ---------------- prep + barrier reset ----------------------------------------
__global__ void prep_kernel(const int* __restrict__ reports,
                            const float* __restrict__ b_ih,
                            const float* __restrict__ b_hh) {
    int j = blockIdx.x * blockDim.x + threadIdx.x;
    if (j == 0) g_barcnt = 0u;
    if (j < G4) g_bsum[j] = b_ih[j] + b_hh[j];
    if (j < B_ * T_) g_idx[j] = ((j & (T_ - 1)) == 0) ? 1 : reports[j - 1];
}

// ---------------- generic NT SGEMM (fc init + xproj) --------------------------
template <bool GATHER>
__global__ void __launch_bounds__(256, 2)
sgemm_nt(const float* __restrict__ A, const float* __restrict__ Bm,
         const float* __restrict__ bias, float* __restrict__ C,
         int M, int N, int K, const int* __restrict__ ridx) {
    const int BM = 128, BN = 128, BK = 8;
    __shared__ float As[BK][BM + 4];
    __shared__ float Bs[BK][BN + 4];

    int bm = blockIdx.y * BM;
    int bn = blockIdx.x * BN;
    int tid = threadIdx.x;

    int lrow = tid >> 1;
    int lk   = (tid & 1) * 4;

    int am = bm + lrow;
    bool aval = (am < M);
    const float* Arow = A;
    if (aval) {
        int r = GATHER ? ridx[am] : am;
        Arow = A + (size_t)r * K;
    }
    const float* Brow = Bm + (size_t)(bn + lrow) * K;

    int tx = tid & 15;
    int ty = tid >> 4;

    float acc[8][8];
#pragma unroll
    for (int i = 0; i < 8; i++)
#pragma unroll
        for (int j = 0; j < 8; j++) acc[i][j] = 0.f;

    for (int k0 = 0; k0 < K; k0 += BK) {
        float4 av = aval ? *(const float4*)(Arow + k0 + lk)
                         : make_float4(0.f, 0.f, 0.f, 0.f);
        float4 bvv = *(const float4*)(Brow + k0 + lk);
        As[lk + 0][lrow] = av.x;  As[lk + 1][lrow] = av.y;
        As[lk + 2][lrow] = av.z;  As[lk + 3][lrow] = av.w;
        Bs[lk + 0][lrow] = bvv.x; Bs[lk + 1][lrow] = bvv.y;
        Bs[lk + 2][lrow] = bvv.z; Bs[lk + 3][lrow] = bvv.w;
        __syncthreads();

#pragma unroll
        for (int kk = 0; kk < BK; kk++) {
            float4 a0 = *(const float4*)&As[kk][ty * 8];
            float4 a1 = *(const float4*)&As[kk][ty * 8 + 4];
            float4 b0 = *(const float4*)&Bs[kk][tx * 8];
            float4 b1 = *(const float4*)&Bs[kk][tx * 8 + 4];
            float a[8] = {a0.x, a0.y, a0.z, a0.w, a1.x, a1.y, a1.z, a1.w};
            float b[8] = {b0.x, b0.y, b0.z, b0.w, b1.x, b1.y, b1.z, b1.w};
#pragma unroll
            for (int i = 0; i < 8; i++)
#pragma unroll
                for (int j = 0; j < 8; j++) acc[i][j] += a[i] * b[j];
        }
        __syncthreads();
    }

#pragma unroll
    for (int i = 0; i < 8; i++) {
        int m = bm + ty * 8 + i;
        if (m < M) {
            float* Crow = C + (size_t)m * N + bn + tx * 8;
#pragma unroll
            for (int j = 0; j < 8; j++)
                Crow[j] = acc[i][j] + bias[bn + tx * 8 + j];
        }
    }
}

// ---------------- bf16 split conversions ([hi|lo|hi] row layout) --------------
__global__ void conv_split_kernel(const float* __restrict__ S,
                                  __nv_bfloat16* __restrict__ D, int total) {
    int i = blockIdx.x * blockDim.x + threadIdx.x;
    if (i >= total) return;
    float x = S[i];
    int m = i >> 10, k = i & 1023;
    __nv_bfloat16 hi = __float2bfloat16(x);
    __nv_bfloat16 lo = __float2bfloat16(x - __bfloat162float(hi));
    __nv_bfloat16* r = D + (size_t)m * KC;
    r[k] = hi; r[k + 1024] = lo; r[k + 2048] = hi;
}

// ---------------- mma helpers --------------------------------------------------
__device__ __forceinline__ void mma_bf16(float* d, const uint32_t* a,
                                         const uint32_t* b) {
    asm volatile(
        "mma.sync.aligned.m16n8k16.row.col.f32.bf16.bf16.f32 "
        "{%0,%1,%2,%3}, {%4,%5,%6,%7}, {%8,%9}, {%0,%1,%2,%3};"
        : "+f"(d[0]), "+f"(d[1]), "+f"(d[2]), "+f"(d[3])
        : "r"(a[0]), "r"(a[1]), "r"(a[2]), "r"(a[3]), "r"(b[0]), "r"(b[1]));
}
#define XB32(row, kp) (((row) << 4) + ((kp) ^ (((row) & 6) << 1)))

__device__ __forceinline__ float sigmoidf_(float x) {
    return 1.f / (1.f + expf(-x));
}

// ---------------- persistent tensor-core LSTM ---------------------------------
// 128 blocks x 256 threads, 1 block/SM (224KB smem). Block bi owns hidden units
// u0=8*bi..u0+7 -> 32 gate rows {g*1024+u0+i}. W slice (32x3072 bf16 split)
// resident in SMEM. Per step: C[32b x 32rows] = A(h split) @ Wslice^T via mma,
// + xproj, cell update (c in regs), h split written to g_A2 row (b*T+t).
// Grid-wide sense barrier between steps (monotonic atomic counter).
__global__ void __launch_bounds__(256, 1)
lstm_persistent() {
    extern __shared__ char smem[];
    uint32_t* sW = (uint32_t*)smem;                    // 96 slabs x 512 b32 = 192KB
    uint32_t* sA = (uint32_t*)(smem + 196608);         // 2 bufs x 8 slabs x 512 b32 = 32KB
    float*  Csum = (float*)(smem + 196608);            // overlay on sA (16.9KB)

    int tid = threadIdx.x;
    int lane = tid & 31, w = tid >> 5;
    int g = lane >> 2, tig = lane & 3;
    int wm = w >> 2, wk = w & 3;     // m-half, k-interleave class
    int u0 = blockIdx.x * 8;

    // ---- one-time: stage W slice into smem (rows r=0..31 -> grow) ----
    {
        int r = tid >> 3, e = tid & 7;
        int grow = ((r >> 3) << 10) + u0 + (r & 7);
        const uint4* wrow = (const uint4*)(g_W2 + (size_t)grow * KC);
        int sw = (r & 6) << 1;
#pragma unroll 4
        for (int j = 0; j < 48; j++) {
            int idx = e + j * 8;              // uint4 index within 384
            uint4 v = wrow[idx];
            int s = idx >> 2, q = (idx & 3) * 4;
            *(uint4*)&sW[s * 512 + r * 16 + (q ^ sw)] = v;
        }
    }

    // ---- init c (regs) and write h0 split to g_A0 ----
    int cb = tid >> 3, cu = tid & 7;
    int uu = u0 + cu;
    float creg = g_init[cb * 2 * H_ + H_ + uu];
    {
        float h0 = g_init[cb * 2 * H_ + uu];
        __nv_bfloat16 hi = __float2bfloat16(h0);
        __nv_bfloat16 lo = __float2bfloat16(h0 - __bfloat162float(hi));
        __nv_bfloat16* r = g_A0 + cb * KC;
        r[uu] = hi; r[uu + 1024] = hi; r[uu + 2048] = lo;
    }
    __threadfence();

    // ---- grid barrier helper state ----
    unsigned epoch = 0;
    volatile unsigned* vb = &g_barcnt;
    // barrier: arrive + spin (thread 0), block-wide sync around it
#define GRIDBAR() do {                                              \
        __syncthreads();                                            \
        epoch++;                                                    \
        if (tid == 0) {                                             \
            atomicAdd(&g_barcnt, 1u);                               \
            while (*vb < epoch * (unsigned)NBLK) {}                 \
            __threadfence();                                        \
        }                                                           \
        __syncthreads();                                            \
    } while (0)

    GRIDBAR();   // h0 split visible everywhere

    int lr = tid >> 3, le = tid & 7;       // A-stage loader mapping
    int lsw = (lr & 6) << 1;

    for (int t = 0; t < T_; t++) {
        const __nv_bfloat16* Abase =
            (t == 0) ? (g_A0 + lr * KC)
                     : (g_A2 + ((size_t)(lr * T_ + (t - 1))) * KC);
        const uint4* arow = (const uint4*)Abase;

        float acc[4][4];
#pragma unroll
        for (int i = 0; i < 4; i++)
#pragma unroll
            for (int q = 0; q < 4; q++) acc[i][q] = 0.f;

        // stage chunk 0
#pragma unroll
        for (int j = 0; j < 4; j++) {
            int cu4 = le + j * 8;                     // uint4 col within chunk (0..31)
            uint4 v = arow[cu4];
            int s = cu4 >> 2, q = (cu4 & 3) * 4;
            *(uint4*)&sA[s * 512 + lr * 16 + (q ^ lsw)] = v;
        }
        __syncthreads();

        // 12 chunks of 256 k (8 slabs), double-buffered
        for (int kc = 0; kc < 12; kc++) {
            int p = kc & 1;
            if (kc + 1 < 12) {
                int pb = p ^ 1;
#pragma unroll
                for (int j = 0; j < 4; j++) {
                    int cu4 = le + j * 8;
                    uint4 v = arow[(kc + 1) * 32 + cu4];
                    int s = cu4 >> 2, q = (cu4 & 3) * 4;
                    *(uint4*)&sA[pb * 4096 + s * 512 + lr * 16 + (q ^ lsw)] = v;
                }
            }
            // this warp's 4 k16-steps within chunk: j16 = jj*4 + wk
            const uint32_t* cA = sA + p * 4096;
#pragma unroll
            for (int jj = 0; jj < 4; jj++) {
                int j16 = jj * 4 + wk;
                int s = j16 >> 1, h = j16 & 1;
                int kp1 = h * 8 + tig, kp2 = kp1 + 4;
                int ab = s * 512;
                uint32_t af[4];
                int r1 = wm * 16 + g, r2 = r1 + 8;
                af[0] = cA[ab + XB32(r1, kp1)];
                af[1] = cA[ab + XB32(r2, kp1)];
                af[2] = cA[ab + XB32(r1, kp2)];
                af[3] = cA[ab + XB32(r2, kp2)];
                const uint32_t* cW = sW + (kc * 8 + s) * 512;
#pragma unroll
                for (int nt = 0; nt < 4; nt++) {
                    uint32_t bf[2];
                    bf[0] = cW[XB32(nt * 8 + g, kp1)];
                    bf[1] = cW[XB32(nt * 8 + g, kp2)];
                    mma_bf16(acc[nt], af, bf);
                }
            }
            __syncthreads();
        }

        // partial-sum reduction via smem (overlay on sA; prior sync done)
#pragma unroll
        for (int nt = 0; nt < 4; nt++) {
#pragma unroll
            for (int i2 = 0; i2 < 2; i2++) {
                int m = wm * 16 + g + i2 * 8;
                int n = nt * 8 + 2 * tig;
                Csum[(wk * 32 + m) * 33 + n]     = acc[nt][i2 * 2];
                Csum[(wk * 32 + m) * 33 + n + 1] = acc[nt][i2 * 2 + 1];
            }
        }
        __syncthreads();

        // cell update: thread -> (batch cb, unit cu)
        const float* xp = g_xproj + ((size_t)(cb * T_ + t)) * G4 + uu;
        float gate[4];
#pragma unroll
        for (int g4 = 0; g4 < 4; g4++) {
            int n = g4 * 8 + cu;
            gate[g4] = Csum[(0 * 32 + cb) * 33 + n] + Csum[(1 * 32 + cb) * 33 + n]
                     + Csum[(2 * 32 + cb) * 33 + n] + Csum[(3 * 32 + cb) * 33 + n]
                     + xp[g4 * 1024];
        }
        float cn = sigmoidf_(gate[1]) * creg + sigmoidf_(gate[0]) * tanhf(gate[2]);
        float hn = sigmoidf_(gate[3]) * tanhf(cn);
        creg = cn;
        {
            __nv_bfloat16 hi = __float2bfloat16(hn);
            __nv_bfloat16 lo = __float2bfloat16(hn - __bfloat162float(hi));
            __nv_bfloat16* r = g_A2 + ((size_t)(cb * T_ + t)) * KC;
            r[uu] = hi; r[uu + 1024] = hi; r[uu + 2048] = lo;
        }
        __threadfence();
        GRIDBAR();
    }
#undef GRIDBAR
}

// ---------------- mma.sync bf16 GEMM: out = A2 @ B2^T + bv --------------------
__global__ void __launch_bounds__(256, 2)
mma_gemm_out(const __nv_bfloat16* __restrict__ A2,
             const __nv_bfloat16* __restrict__ B2,
             const float* __restrict__ bias,
             float* __restrict__ C) {
    __shared__ uint32_t sA[2][128 * 16];
    __shared__ uint32_t sB[2][128 * 16];

    int tid = threadIdx.x;
    int lane = tid & 31, w = tid >> 5;
    int g = lane >> 2, tig = lane & 3;
    int wm = w >> 2, wn = w & 3;

    int m0 = blockIdx.x * 128;
    int n0 = blockIdx.y * 128;

    int lrow = tid >> 1;
    int lhalf = tid & 1;
    const uint4* pa = (const uint4*)(A2 + (size_t)(m0 + lrow) * KC) + lhalf * 2;
    const uint4* pb = (const uint4*)(B2 + (size_t)(n0 + lrow) * KC) + lhalf * 2;
    int sw = lrow & 6;
    int st0 = (lrow << 4) + (((lhalf * 4 + 0) ^ sw) << 1);
    int st1 = (lrow << 4) + (((lhalf * 4 + 2) ^ sw) << 1);

    float acc[4][4][4];
#pragma unroll
    for (int i = 0; i < 4; i++)
#pragma unroll
        for (int j = 0; j < 4; j++)
#pragma unroll
            for (int q = 0; q < 4; q++) acc[i][j][q] = 0.f;

    uint4 ra0 = pa[0], ra1 = pa[1];
    uint4 rb0 = pb[0], rb1 = pb[1];

    for (int kc = 0; kc < NKCH; kc++) {
        int p = kc & 1;
        *(uint4*)&sA[p][st0] = ra0;
        *(uint4*)&sA[p][st1] = ra1;
        *(uint4*)&sB[p][st0] = rb0;
        *(uint4*)&sB[p][st1] = rb1;
        __syncthreads();

        if (kc + 1 < NKCH) {
            ra0 = pa[(kc + 1) * 4 + 0]; ra1 = pa[(kc + 1) * 4 + 1];
            rb0 = pb[(kc + 1) * 4 + 0]; rb1 = pb[(kc + 1) * 4 + 1];
        }

        const uint32_t* cA = sA[p];
        const uint32_t* cB = sB[p];
#pragma unroll
        for (int ks = 0; ks < 2; ks++) {
            int kp1 = ks * 8 + tig;
            int kp2 = kp1 + 4;
            uint32_t bf[4][2];
#pragma unroll
            for (int nt = 0; nt < 4; nt++) {
                int rb = wn * 32 + nt * 8 + g;
                bf[nt][0] = cB[XB32(rb, kp1)];
                bf[nt][1] = cB[XB32(rb, kp2)];
            }
#pragma unroll
            for (int mt = 0; mt < 4; mt++) {
                int r1 = wm * 64 + mt * 16 + g;
                int r2 = r1 + 8;
                uint32_t af[4];
                af[0] = cA[XB32(r1, kp1)];
                af[1] = cA[XB32(r2, kp1)];
                af[2] = cA[XB32(r1, kp2)];
                af[3] = cA[XB32(r2, kp2)];
#pragma unroll
                for (int nt = 0; nt < 4; nt++)
                    mma_bf16(acc[mt][nt], af, bf[nt]);
            }
        }
        __syncthreads();
    }

#pragma unroll
    for (int mt = 0; mt < 4; mt++) {
#pragma unroll
        for (int i2 = 0; i2 < 2; i2++) {
            int row = m0 + wm * 64 + mt * 16 + g + i2 * 8;
            float* crow = C + (size_t)row * V_;
#pragma unroll
            for (int nt = 0; nt < 4; nt++) {
                int col = n0 + wn * 32 + nt * 8 + 2 * tig;
                float b0 = __ldg(&bias[col]);
                float b1 = __ldg(&bias[col + 1]);
                crow[col]     = acc[mt][nt][i2 * 2]     + b0;
                crow[col + 1] = acc[mt][nt][i2 * 2 + 1] + b1;
            }
        }
    }
}

// ---------------- launcher ---------------------------------------------------
extern "C" void kernel_launch(void* const* d_in, const int* in_sizes, int n_in,
                              void* d_out, int out_size) {
    const float* features = (const float*)d_in[0];
    const int*   reports  = (const int*)d_in[1];
    const float* fc_W     = (const float*)d_in[2];
    const float* fc_b     = (const float*)d_in[3];
    const float* emb      = (const float*)d_in[4];
    const float* W_ih     = (const float*)d_in[5];
    const float* W_hh     = (const float*)d_in[6];
    const float* b_ih     = (const float*)d_in[7];
    const float* b_hh     = (const float*)d_in[8];
    const float* Wv       = (const float*)d_in[9];
    const float* bv       = (const float*)d_in[10];
    float* out = (float*)d_out;

    float *pooled_p, *init_p, *xproj_p, *bsum_p;
    __nv_bfloat16 *A2_p, *B2_p;
    int* idx_p;
    cudaGetSymbolAddress((void**)&pooled_p, g_pooled);
    cudaGetSymbolAddress((void**)&init_p,   g_init);
    cudaGetSymbolAddress((void**)&xproj_p,  g_xproj);
    cudaGetSymbolAddress((void**)&bsum_p,   g_bsum);
    cudaGetSymbolAddress((void**)&idx_p,    g_idx);
    cudaGetSymbolAddress((void**)&A2_p,     g_A2);
    cudaGetSymbolAddress((void**)&B2_p,     g_B2);
    __nv_bfloat16* W2_p;
    cudaGetSymbolAddress((void**)&W2_p,     g_W2);

    cudaFuncSetAttribute(lstm_persistent,
                         cudaFuncAttributeMaxDynamicSharedMemorySize, 229376);

    // 1) pooling
    pool_kernel<<<(B_ * F_ + 255) / 256, 256>>>(features);

    // 2) fc init: init(32x2048) = pooled @ fc_W^T + fc_b
    sgemm_nt<false><<<dim3((2 * H_) / 128, 1), 256>>>(
        pooled_p, fc_W, fc_b, init_p, B_, 2 * H_, F_, nullptr);

    // 3) prep (bsum, idx, barrier reset)
    prep_kernel<<<(B_ * H_ + 255) / 256, 256>>>(reports, b_ih, b_hh);

    // 4) weight splits (independent of recurrence)
    conv_split_kernel<<<(V_ * H_ + 255) / 256, 256>>>(Wv, B2_p, V_ * H_);
    conv_split_kernel<<<(G4 * H_ + 255) / 256, 256>>>(W_hh, W2_p, G4 * H_);

    // 5) xproj(4096x4096) = emb[idx] @ W_ih^T + (b_ih + b_hh)
    sgemm_nt<true><<<dim3(G4 / 128, (B_ * T_) / 128), 256>>>(
        emb, W_ih, bsum_p, xproj_p, B_ * T_, G4, E_, idx_p);

    // 6) persistent tensor-core LSTM (all 128 steps)
    lstm_persistent<<<NBLK, 256, 229376>>>();

    // 7) output projection on tensor cores
    mma_gemm_out<<<dim3((B_ * T_) / 128, V_ / 128), 256>>>(
        A2_p, B2_p, bv, out);
}